// round 15
// baseline (speedup 1.0000x reference)
#include <cuda_runtime.h>
#include <cuda_fp16.h>
#include <cstdint>
#include <math.h>

#define BB 4
#define LL 2048
#define DD 1024
#define HH 16
#define KK 256
#define DH 64
#define MROWS (BB*LL)   // 8192

// ---- scratch (device globals; no runtime allocation allowed) ----
__device__ float g_q[BB*LL*DD];        // x @ Wq^T            [B,L,D]
__device__ float g_xkt[BB*DD*LL];      // (x @ Wk^T)^T        [B,D,L]
__device__ float g_xvt[BB*DD*LL];      // (x @ Wv^T)^T        [B,D,L]
__device__ float g_projkt[KK*LL];      // proj_k^T            [K,L]
__device__ float g_projvt[KK*LL];      // proj_v^T            [K,L]
__device__ float g_keys2[2*BB*KK*DD];  // split-K partials (summed in attn)
__device__ float g_vals2[2*BB*KK*DD];
__device__ float g_ctx[BB*LL*DD];      // attention out       [B,L,D]

// ============================================================
// helpers
// ============================================================
__device__ __forceinline__ uint32_t smem_u32(const void* p) {
    uint32_t a;
    asm("{ .reg .u64 t; cvta.to.shared.u64 t, %1; cvt.u32.u64 %0, t; }"
        : "=r"(a) : "l"(p));
    return a;
}
__device__ __forceinline__ void ldsm4(uint32_t* r, uint32_t addr) {
    asm volatile("ldmatrix.sync.aligned.m8n8.x4.shared.b16 {%0,%1,%2,%3}, [%4];"
        : "=r"(r[0]), "=r"(r[1]), "=r"(r[2]), "=r"(r[3]) : "r"(addr));
}
__device__ __forceinline__ void ldsm2(uint32_t* r, uint32_t addr) {
    asm volatile("ldmatrix.sync.aligned.m8n8.x2.shared.b16 {%0,%1}, [%2];"
        : "=r"(r[0]), "=r"(r[1]) : "r"(addr));
}
__device__ __forceinline__ void ldsm4t(uint32_t* r, uint32_t addr) {
    asm volatile("ldmatrix.sync.aligned.m8n8.x4.trans.shared.b16 {%0,%1,%2,%3}, [%4];"
        : "=r"(r[0]), "=r"(r[1]), "=r"(r[2]), "=r"(r[3]) : "r"(addr));
}
__device__ __forceinline__ void mma16816(float* c, const uint32_t* a, const uint32_t* b) {
    asm volatile(
        "mma.sync.aligned.m16n8k16.row.col.f32.f16.f16.f32 "
        "{%0,%1,%2,%3}, {%4,%5,%6,%7}, {%8,%9}, {%0,%1,%2,%3};"
        : "+f"(c[0]), "+f"(c[1]), "+f"(c[2]), "+f"(c[3])
        : "r"(a[0]), "r"(a[1]), "r"(a[2]), "r"(a[3]), "r"(b[0]), "r"(b[1]));
}
#define BAR_SYNC(id)   asm volatile("bar.sync %0, 384;"   :: "r"(id) : "memory")
#define BAR_ARRIVE(id) asm volatile("bar.arrive %0, 384;" :: "r"(id) : "memory")

// split 8 f32 -> 16B hi chunk + 16B lo chunk
__device__ __forceinline__ void cvt_split16(float4 a, float4 b, uint4& hi, uint4& lo) {
    __half2 h0 = __floats2half2_rn(a.x, a.y);
    __half2 h1 = __floats2half2_rn(a.z, a.w);
    __half2 h2 = __floats2half2_rn(b.x, b.y);
    __half2 h3 = __floats2half2_rn(b.z, b.w);
    float2 f0 = __half22float2(h0);
    float2 f1 = __half22float2(h1);
    float2 f2 = __half22float2(h2);
    float2 f3 = __half22float2(h3);
    __half2 l0 = __floats2half2_rn(a.x - f0.x, a.y - f0.y);
    __half2 l1 = __floats2half2_rn(a.z - f1.x, a.w - f1.y);
    __half2 l2 = __floats2half2_rn(b.x - f2.x, b.y - f2.y);
    __half2 l3 = __floats2half2_rn(b.z - f3.x, b.w - f3.y);
    hi.x = *(uint32_t*)&h0; hi.y = *(uint32_t*)&h1;
    hi.z = *(uint32_t*)&h2; hi.w = *(uint32_t*)&h3;
    lo.x = *(uint32_t*)&l0; lo.y = *(uint32_t*)&l1;
    lo.z = *(uint32_t*)&l2; lo.w = *(uint32_t*)&l3;
}
// round 8 f32 -> 16B fp16 chunk (hi only)
__device__ __forceinline__ void cvt_hi16(float4 a, float4 b, uint4& hi) {
    __half2 h0 = __floats2half2_rn(a.x, a.y);
    __half2 h1 = __floats2half2_rn(a.z, a.w);
    __half2 h2 = __floats2half2_rn(b.x, b.y);
    __half2 h3 = __floats2half2_rn(b.z, b.w);
    hi.x = *(uint32_t*)&h0; hi.y = *(uint32_t*)&h1;
    hi.z = *(uint32_t*)&h2; hi.w = *(uint32_t*)&h3;
}

// ============================================================
// Shared GEMM body constants (BK=64, 2-stage, 128x128 tile)
// ============================================================
#define T64B 16384                    // one plane: 128 rows x 128B
#define STG64B (3*T64B)               // A_hi, B_hi, B_lo = 49152
#define GEMM64_SMEM (2*STG64B)        // 98304

// ---- producer body (shared by gemm_big / gemm3) ----
__device__ __forceinline__ void big_producer(
    char* smc, const float* A, const float* B, int lda, int ldb,
    int m0, int n0, int iters, int tid)
{
    const int ptid = tid - 256;
    const float* Aip = A + (size_t)m0 * lda;
    const float* Bip = B + (size_t)n0 * ldb;

    for (int it = 0; it < iters; it++) {
        const int s = it & 1;
        if (it >= 2) BAR_SYNC(4 + s);             // EMPTY(s)
        const int k0 = it * 64;
        char* stg = smc + s * STG64B;
        #pragma unroll
        for (int p = 0; p < 8; p++) {
            int idx = ptid + p * 128;             // 0..1023
            int r = idx >> 3, c = idx & 7;
            int sw = r * 128 + ((c ^ (r & 7)) << 4);
            const float* src = Aip + (size_t)r * lda + k0 + c * 8;
            float4 v0 = *(const float4*)src;
            float4 v1 = *(const float4*)(src + 4);
            uint4 hi;
            cvt_hi16(v0, v1, hi);
            *(uint4*)(stg + sw) = hi;
        }
        #pragma unroll
        for (int p = 0; p < 8; p++) {
            int idx = ptid + p * 128;
            int r = idx >> 3, c = idx & 7;
            int sw = r * 128 + ((c ^ (r & 7)) << 4);
            const float* src = Bip + (size_t)r * ldb + k0 + c * 8;
            float4 v0 = *(const float4*)src;
            float4 v1 = *(const float4*)(src + 4);
            uint4 hi, lo;
            cvt_split16(v0, v1, hi, lo);
            *(uint4*)(stg + T64B + sw) = hi;
            *(uint4*)(stg + 2*T64B + sw) = lo;
        }
        BAR_ARRIVE(1 + s);                        // FULL(s)
    }
}

// ---- consumer body (software-pipelined fragments) ----
template<bool BIAS>
__device__ __forceinline__ void big_consumer(
    char* smc, float* C, int ldc, const float* bias,
    int m0, int n0, int iters, int tid)
{
    const int lane = tid & 31;
    const int wid  = tid >> 5;
    const int wm = wid >> 2;
    const int wn = wid & 3;
    const int g  = lane >> 2;
    const int tig = lane & 3;
    const uint32_t sbase = smem_u32(smc);
    const int grp = lane >> 3;
    const int bt  = lane & 7;

    float acc[4][4][4];
    #pragma unroll
    for (int i = 0; i < 4; i++)
        #pragma unroll
        for (int j = 0; j < 4; j++)
            #pragma unroll
            for (int v = 0; v < 4; v++) acc[i][j][v] = 0.f;

    uint32_t ah[2][4][4], bh[2][4][2], bl[2][4][2];

    auto load_frags = [&](uint32_t stg, int kt, int buf) {
        const int cA = kt * 2 + (lane >> 4);
        #pragma unroll
        for (int mi = 0; mi < 4; mi++) {
            int r = wm * 64 + mi * 16 + (lane & 15);
            uint32_t off = (uint32_t)(r * 128 + ((cA ^ (r & 7)) << 4));
            ldsm4(ah[buf][mi], stg + off);
        }
        #pragma unroll
        for (int nip = 0; nip < 2; nip++) {
            int row = wn * 32 + nip * 16 + ((grp >> 1) << 3) + bt;
            int cc  = kt * 2 + (grp & 1);
            uint32_t off = (uint32_t)(row * 128 + ((cc ^ (row & 7)) << 4));
            uint32_t r4[4];
            ldsm4(r4, stg + T64B + off);
            bh[buf][nip*2][0]   = r4[0]; bh[buf][nip*2][1]   = r4[1];
            bh[buf][nip*2+1][0] = r4[2]; bh[buf][nip*2+1][1] = r4[3];
            ldsm4(r4, stg + 2*T64B + off);
            bl[buf][nip*2][0]   = r4[0]; bl[buf][nip*2][1]   = r4[1];
            bl[buf][nip*2+1][0] = r4[2]; bl[buf][nip*2+1][1] = r4[3];
        }
    };

    for (int it = 0; it < iters; it++) {
        const int s = it & 1;
        BAR_SYNC(1 + s);                          // FULL(s)
        const uint32_t stg = sbase + s * STG64B;

        load_frags(stg, 0, 0);
        #pragma unroll
        for (int kt = 0; kt < 4; kt++) {
            const int cur = kt & 1;
            if (kt < 3) load_frags(stg, kt + 1, cur ^ 1);
            #pragma unroll
            for (int mi = 0; mi < 4; mi++)
                #pragma unroll
                for (int ni = 0; ni < 4; ni++) {
                    mma16816(acc[mi][ni], ah[cur][mi], bh[cur][ni]);
                    mma16816(acc[mi][ni], ah[cur][mi], bl[cur][ni]);
                }
        }
        BAR_ARRIVE(4 + s);                        // EMPTY(s)
    }

    #pragma unroll
    for (int mi = 0; mi < 4; mi++) {
        const int r0 = m0 + wm * 64 + mi * 16 + g;
        #pragma unroll
        for (int ni = 0; ni < 4; ni++) {
            const int col = n0 + wn * 32 + ni * 8 + tig * 2;
            float2 v0, v1;
            v0.x = acc[mi][ni][0]; v0.y = acc[mi][ni][1];
            v1.x = acc[mi][ni][2]; v1.y = acc[mi][ni][3];
            if (BIAS) {
                float2 bv = *(const float2*)(bias + col);
                v0.x += bv.x; v0.y += bv.y;
                v1.x += bv.x; v1.y += bv.y;
            }
            *(float2*)(C + (size_t)r0 * ldc + col) = v0;
            *(float2*)(C + (size_t)(r0 + 8) * ldc + col) = v1;
        }
    }
}

// ============================================================
// gemm_big: single-problem BK=64 GEMM (used for out-GEMM)
// ============================================================
template<bool BIAS>
__global__ __launch_bounds__(384, 1)
void gemm_big(const float* __restrict__ A, long Ab, int lda,
              const float* __restrict__ B, long Bb, int ldb,
              float* __restrict__ C, long Cb, int ldc,
              const float* __restrict__ bias, int Kd)
{
    extern __shared__ __align__(16) char smc[];
    const int tid = threadIdx.x;
    const int z = blockIdx.z;
    const float* Ap = A + (size_t)z * Ab;
    const float* Bp = B + (size_t)z * Bb;
    float* Cp = C + (size_t)z * Cb;
    const int m0 = blockIdx.y * 128;
    const int n0 = blockIdx.x * 128;
    const int iters = Kd / 64;

    if ((tid >> 5) >= 8) big_producer(smc, Ap, Bp, lda, ldb, m0, n0, iters, tid);
    else big_consumer<BIAS>(smc, Cp, ldc, bias, m0, n0, iters, tid);
}

// ============================================================
// gemm3: q + xkt + xvt merged (1536 CTAs, flattened 1D grid)
// ============================================================
__global__ __launch_bounds__(384, 1)
void gemm3(const float* __restrict__ x,
           const float* __restrict__ Wq,
           const float* __restrict__ Wk,
           const float* __restrict__ Wv,
           float* __restrict__ q,
           float* __restrict__ xkt,
           float* __restrict__ xvt)
{
    extern __shared__ __align__(16) char smc[];
    const int tid = threadIdx.x;
    int t = blockIdx.x;

    const float *A, *B;
    float* C;
    int m0, n0, ldb, ldc;
    if (t < 512) {
        A = x; B = Wq; C = q;
        m0 = (t >> 3) * 128; n0 = (t & 7) * 128;
        ldb = DD; ldc = DD;
    } else {
        int which = (t >= 1024);
        int u = t - (which ? 1024 : 512);
        int b = u >> 7;
        int rem = u & 127;
        A = which ? Wv : Wk;
        B = x + (size_t)b * LL * DD;
        C = (which ? xvt : xkt) + (size_t)b * DD * LL;
        m0 = (rem >> 4) * 128; n0 = (rem & 15) * 128;
        ldb = DD; ldc = LL;
    }

    if ((tid >> 5) >= 8) big_producer(smc, A, B, DD, ldb, m0, n0, DD / 64, tid);
    else big_consumer<false>(smc, C, ldc, nullptr, m0, n0, DD / 64, tid);
}

// ============================================================
// 128x128 BK=32 warp-specialized 2-MMA split GEMM (proj GEMMs, merged)
// ============================================================
#define TILEB 8192
#define STGB  (3*TILEB)
#define NSTG  3
#define GEMM_SMEM (NSTG*STGB)        // 73728

__global__ __launch_bounds__(384, 1)
void gemm_ws(const float* __restrict__ A0, const float* __restrict__ A1,
             long Ab, int lda,
             const float* __restrict__ B0, const float* __restrict__ B1,
             long Bb, int ldb,
             float* __restrict__ C0, float* __restrict__ C1,
             long Cb, long Cs, int ldc,
             int Kd, int ksp, int zhalf)
{
    extern __shared__ __align__(16) char smc[];

    const int tid  = threadIdx.x;
    const int lane = tid & 31;
    const int wid  = tid >> 5;

    int z = blockIdx.z;
    const float* A = A0;
    const float* B = B0;
    float* C = C0;
    if (z >= zhalf) { A = A1; B = B1; C = C1; z -= zhalf; }
    const int zb = z / ksp;
    const int zs = z % ksp;
    A += (size_t)zb * Ab + (size_t)zs * Kd;
    B += (size_t)zb * Bb + (size_t)zs * Kd;
    C += (size_t)zb * Cb + (size_t)zs * Cs;
    const int m0 = blockIdx.y * 128;
    const int n0 = blockIdx.x * 128;
    const int iters = Kd / 32;

    if (wid >= 8) {
        const int ptid = tid - 256;
        const float* Aip = A + (size_t)m0 * lda;
        const float* Bip = B + (size_t)n0 * ldb;

        for (int it = 0; it < iters; it++) {
            const int s = it % NSTG;
            if (it >= NSTG) BAR_SYNC(4 + s);
            const int k0 = it * 32;
            char* stg = smc + s * STGB;
            #pragma unroll
            for (int p = 0; p < 4; p++) {
                int idx = ptid + p * 128;
                int r = idx >> 2, c = idx & 3;
                int sw = (c ^ ((r >> 1) & 3)) * 16;
                {
                    const float* src = Aip + (size_t)r * lda + k0 + c * 8;
                    float4 v0 = *(const float4*)src;
                    float4 v1 = *(const float4*)(src + 4);
                    uint4 hi;
                    cvt_hi16(v0, v1, hi);
                    *(uint4*)(stg + r * 64 + sw) = hi;
                }
                {
                    const float* src = Bip + (size_t)r * ldb + k0 + c * 8;
                    float4 v0 = *(const float4*)src;
                    float4 v1 = *(const float4*)(src + 4);
                    uint4 hi, lo;
                    cvt_split16(v0, v1, hi, lo);
                    *(uint4*)(stg + TILEB + r * 64 + sw) = hi;
                    *(uint4*)(stg + 2*TILEB + r * 64 + sw) = lo;
                }
            }
            BAR_ARRIVE(1 + s);
        }
    } else {
        const int wm = wid >> 2;
        const int wn = wid & 3;
        const int g  = lane >> 2;
        const int tig = lane & 3;
        const uint32_t sbase = smem_u32(smc);

        float acc[4][4][4];
        #pragma unroll
        for (int i = 0; i < 4; i++)
            #pragma unroll
            for (int j = 0; j < 4; j++)
                #pragma unroll
                for (int v = 0; v < 4; v++) acc[i][j][v] = 0.f;

        for (int it = 0; it < iters; it++) {
            const int s = it % NSTG;
            BAR_SYNC(1 + s);
            const uint32_t stg = sbase + s * STGB;

            uint32_t ah[2][4][4], bh[2][4][2], bl[2][4][2];
            #pragma unroll
            for (int ks = 0; ks < 2; ks++) {
                const int cA = ks * 2 + (lane >> 4);
                #pragma unroll
                for (int mi = 0; mi < 4; mi++) {
                    int r = wm * 64 + mi * 16 + (lane & 15);
                    uint32_t off = (uint32_t)(r * 64 + ((cA ^ ((r >> 1) & 3)) << 4));
                    ldsm4(ah[ks][mi], stg + off);
                }
                const int cB = ks * 2 + ((lane >> 3) & 1);
                #pragma unroll
                for (int ni = 0; ni < 4; ni++) {
                    int r = wn * 32 + ni * 8 + (lane & 7);
                    uint32_t off = (uint32_t)(r * 64 + ((cB ^ ((r >> 1) & 3)) << 4));
                    ldsm2(bh[ks][ni], stg + TILEB + off);
                    ldsm2(bl[ks][ni], stg + 2*TILEB + off);
                }
            }
            #pragma unroll
            for (int ks = 0; ks < 2; ks++)
                #pragma unroll
                for (int mi = 0; mi < 4; mi++)
                    #pragma unroll
                    for (int ni = 0; ni < 4; ni++) {
                        mma16816(acc[mi][ni], ah[ks][mi], bh[ks][ni]);
                        mma16816(acc[mi][ni], ah[ks][mi], bl[ks][ni]);
                    }
            BAR_ARRIVE(4 + s);
        }

        #pragma unroll
        for (int mi = 0; mi < 4; mi++) {
            const int r0 = m0 + wm * 64 + mi * 16 + g;
            #pragma unroll
            for (int ni = 0; ni < 4; ni++) {
                const int col = n0 + wn * 32 + ni * 8 + tig * 2;
                float2 v0, v1;
                v0.x = acc[mi][ni][0]; v0.y = acc[mi][ni][1];
                v1.x = acc[mi][ni][2]; v1.y = acc[mi][ni][3];
                *(float2*)(C + (size_t)r0 * ldc + col) = v0;
                *(float2*)(C + (size_t)(r0 + 8) * ldc + col) = v1;
            }
        }
    }
}

// ============================================================
// proj transpose: [L,K] -> [K,L]
// ============================================================
__global__ __launch_bounds__(256)
void transpose_proj(const float* __restrict__ pk, const float* __restrict__ pv,
                    float* __restrict__ okt, float* __restrict__ ovt)
{
    __shared__ float t[32][33];
    const float* src = blockIdx.z ? pv : pk;
    float* dst       = blockIdx.z ? ovt : okt;
    int k0 = blockIdx.x * 32, l0 = blockIdx.y * 32;
    int tx = threadIdx.x, ty = threadIdx.y;
    #pragma unroll
    for (int i = 0; i < 32; i += 8)
        t[ty + i][tx] = src[(size_t)(l0 + ty + i) * KK + k0 + tx];
    __syncthreads();
    #pragma unroll
    for (int i = 0; i < 32; i += 8)
        dst[(size_t)(k0 + ty + i) * LL + l0 + tx] = t[tx][ty + i];
}

// ============================================================
// MMA attention: online-softmax 2-chunk (128 cols each), 2-MMA split.
// acc registers reused across chunks -> ~170 regs (no spill).
// V loaded via ldmatrix.x4.trans. Fused split-K adds for K/V fill.
// ============================================================
#define AQH 0
#define AKH 16384
#define AKL 49152
#define AVH 81920
#define AVL 114688
#define ATTN_SMEM 147456

__global__ __launch_bounds__(256, 1)
void attn_mma()
{
    extern __shared__ __align__(16) char smc[];
    const uint32_t base = smem_u32(smc);

    const int b  = blockIdx.z;
    const int h  = blockIdx.y;
    const int l0 = blockIdx.x * 128;
    const int tid  = threadIdx.x;
    const int lane = tid & 31;
    const int wy   = tid >> 5;
    const int g    = lane >> 2;
    const int tig  = lane & 3;

    // ---- fill Q (hi only) ----
    #pragma unroll
    for (int it = 0; it < 4; it++) {
        int idx = tid + it * 256;
        int r = idx >> 3, c = idx & 7;
        int l = l0 + r;
        const float* src = g_q + ((size_t)(b * LL) + h * 128 + (l >> 4)) * DD
                               + (l & 15) * DH + c * 8;
        float4 v0 = *(const float4*)src;
        float4 v1 = *(const float4*)(src + 4);
        uint4 hi;
        cvt_hi16(v0, v1, hi);
        int sw = r * 128 + ((c ^ (r & 7)) << 4);
        *(uint4*)(smc + AQH + sw) = hi;
    }
    const size_t PART = (size_t)BB * KK * DD;
    // ---- fill K (hi/lo), fused split-K add ----
    #pragma unroll
    for (int it = 0; it < 8; it++) {
        int idx = tid + it * 256;
        int r = idx >> 3, c = idx & 7;
        size_t o = ((size_t)b * KK + r) * DD + h * DH + c * 8;
        float4 a0 = *(const float4*)&g_keys2[o];
        float4 a1 = *(const float4*)&g_keys2[o + 4];
        float4 b0 = *(const float4*)&g_keys2[PART + o];
        float4 b1 = *(const float4*)&g_keys2[PART + o + 4];
        a0.x += b0.x; a0.y += b0.y; a0.z += b0.z; a0.w += b0.w;
        a1.x += b1.x; a1.y += b1.y; a1.z += b1.z; a1.w += b1.w;
        uint4 hi, lo;
        cvt_split16(a0, a1, hi, lo);
        int sw = r * 128 + ((c ^ (r & 7)) << 4);
        *(uint4*)(smc + AKH + sw) = hi;
        *(uint4*)(smc + AKL + sw) = lo;
    }
    // ---- fill V (hi/lo), fused add ----
    #pragma unroll
    for (int it = 0; it < 8; it++) {
        int idx = tid + it * 256;
        int r = idx >> 3, c = idx & 7;
        size_t o = ((size_t)b * KK + r) * DD + h * DH + c * 8;
        float4 a0 = *(const float4*)&g_vals2[o];
        float4 a1 = *(const float4*)&g_vals2[o + 4];
        float4 b0 = *(const float4*)&g_vals2[PART + o];
        float4 b1 = *(const float4*)&g_vals2[PART + o + 4];
        a0.x += b0.x; a0.y += b0.y; a0.z += b0.z; a0.w += b0.w;
        a1.x += b1.x; a1.y += b1.y; a1.z += b1.z; a1.w += b1.w;
        uint4 hi, lo;
        cvt_split16(a0, a1, hi, lo);
        int sw = r * 128 + ((c ^ (r & 7)) << 4);
        *(uint4*)(smc + AVH + sw) = hi;
        *(uint4*)(smc + AVL + sw) = lo;
    }
    __syncthreads();

    const int m0w = wy * 16;

    // ---- Q A-fragments (hi only) ----
    uint32_t qa_h[4][4];
    {
        int r = m0w + (lane & 15);
        #pragma unroll
        for (int kt = 0; kt < 4; kt++) {
            int c = kt * 2 + (lane >> 4);
            uint32_t off = (uint32_t)(r * 128 + ((c ^ (r & 7)) << 4));
            ldsm4(qa_h[kt], base + AQH + off);
        }
    }

    const float SC = 0.125f;
    float bm0 = -1e30f, bm1 = -1e30f;     // running max * SC
    float s0 = 0.f, s1 = 0.f;             // per-lane partial sums
    float oac[8][4];
    #pragma unroll
    for (int nj = 0; nj < 8; nj++)
        #pragma unroll
        for (int v = 0; v < 4; v++) oac[nj][v] = 0.f;

    const int grp = lane >> 3;
    const int bt  = lane & 7;

    #pragma unroll
    for (int ch = 0; ch < 2; ch++) {
        // ---- S chunk = Qh Kh^T + Qh Kl^T  (16 nt of 8 cols) ----
        float acc[16][4];
        #pragma unroll
        for (int nt = 0; nt < 16; nt++)
            #pragma unroll
            for (int v = 0; v < 4; v++) acc[nt][v] = 0.f;

        #pragma unroll
        for (int nt = 0; nt < 16; nt++) {
            int r = (ch * 16 + nt) * 8 + (lane & 7);
            int c0 = (lane >> 3);
            uint32_t off1 = (uint32_t)(r * 128 + ((c0 ^ (r & 7)) << 4));
            uint32_t off2 = (uint32_t)(r * 128 + (((c0 + 4) ^ (r & 7)) << 4));
            uint32_t kh[8], kl[8];
            ldsm4(kh,     base + AKH + off1);
            ldsm4(kh + 4, base + AKH + off2);
            ldsm4(kl,     base + AKL + off1);
            ldsm4(kl + 4, base + AKL + off2);
            #pragma unroll
            for (int kt = 0; kt < 4; kt++) {
                mma16816(acc[nt], qa_h[kt], kh + kt * 2);
                mma16816(acc[nt], qa_h[kt], kl + kt * 2);
            }
        }

        // ---- chunk max (rows g, g+8) ----
        float mx0 = -1e30f, mx1 = -1e30f;
        #pragma unroll
        for (int nt = 0; nt < 16; nt++) {
            mx0 = fmaxf(mx0, fmaxf(acc[nt][0], acc[nt][1]));
            mx1 = fmaxf(mx1, fmaxf(acc[nt][2], acc[nt][3]));
        }
        #pragma unroll
        for (int o = 1; o <= 2; o <<= 1) {
            mx0 = fmaxf(mx0, __shfl_xor_sync(0xffffffffu, mx0, o));
            mx1 = fmaxf(mx1, __shfl_xor_sync(0xffffffffu, mx1, o));
        }
        const float nb0 = fmaxf(bm0, mx0 * SC);
        const float nb1 = fmaxf(bm1, mx1 * SC);
        // rescale running state
        const float f0 = __expf(bm0 - nb0);
        const float f1 = __expf(bm1 - nb1);
        s0 *= f0; s1 *= f1;
        #pragma unroll
        for (int nj = 0; nj < 8; nj++) {
            oac[nj][0] *= f0; oac[nj][1] *= f0;
            oac[nj][2] *= f1; oac[nj][3] *= f1;
        }
        bm0 = nb0; bm1 = nb1;

        // ---- exp + partial sums ----
        #pragma unroll
        for (int nt = 0; nt < 16; nt++) {
            acc[nt][0] = __expf(acc[nt][0] * SC - bm0);
            acc[nt][1] = __expf(acc[nt][1] * SC - bm0);
            acc[nt][2] = __expf(acc[nt][2] * SC - bm1);
            acc[nt][3] = __expf(acc[nt][3] * SC - bm1);
            s0 += acc[nt][0] + acc[nt][1];
            s1 += acc[nt][2] + acc[nt][3];
        }

        // ---- O += Ph Vh + Ph Vl  (V rows ch*128 .. +128) ----
        #pragma unroll
        for (int kt = 0; kt < 8; kt++) {
            uint32_t ph[4];
            #pragma unroll
            for (int half_ = 0; half_ < 2; half_++) {
                const float* c = acc[2 * kt + half_];
                __half2 h0 = __floats2half2_rn(c[0], c[1]);
                __half2 h1 = __floats2half2_rn(c[2], c[3]);
                ph[half_ * 2 + 0] = *(uint32_t*)&h0;
                ph[half_ * 2 + 1] = *(uint32_t*)&h1;
            }
            int rvb = ch * 128 + kt * 16;
            #pragma unroll
            for (int njp = 0; njp < 4; njp++) {
                int row = rvb + (grp & 1) * 8 + bt;
                int cc  = njp * 2 + (grp >> 1);
                uint32_t off = (uint32_t)(row * 128 + ((cc ^ (row & 7)) << 4));
                uint32_t vh[4], vl[4];
                ldsm4t(vh, base + AVH + off);
                ldsm4t(vl, base + AVL + off);
                mma16816(oac[njp*2],     ph, vh);
                mma16816(oac[njp*2],     ph, vl);
                mma16816(oac[njp*2 + 1], ph, vh + 2);
                mma16816(oac[njp*2 + 1], ph, vl + 2);
            }
        }
    }

    // ---- final sums + normalize + store ----
    #pragma unroll
    for (int o = 1; o <= 2; o <<= 1) {
        s0 += __shfl_xor_sync(0xffffffffu, s0, o);
        s1 += __shfl_xor_sync(0xffffffffu, s1, o);
    }
    const float inv0 = 1.f / s0, inv1 = 1.f / s1;

    {
        const int r0 = l0 + m0w + g;
        const size_t orow = ((size_t)(b * LL) + r0) * DD + h * DH;
        #pragma unroll
        for (int nj = 0; nj < 8; nj++) {
            float2 v0, v1;
            v0.x = oac[nj][0] * inv0; v0.y = oac[nj][1] * inv0;
            v1.x = oac[nj][2] * inv1; v1.y = oac[nj][3] * inv1;
            *(float2*)&g_ctx[orow + nj * 8 + tig * 2] = v0;
            *(float2*)&g_ctx[orow + (size_t)8 * DD + nj * 8 + tig * 2] = v1;
        }
    }
}

// ============================================================
extern "C" void kernel_launch(void* const* d_in, const int* in_sizes, int n_in,
                              void* d_out, int out_size)
{
    const float* x      = (const float*)d_in[0];
    const float* Wq     = (const float*)d_in[1];
    const float* Wk     = (const float*)d_in[2];
    const float* Wv     = (const float*)d_in[3];
    const float* proj_k = (const float*)d_in[4];
    const float* proj_v = (const float*)d_in[5];
    const float* Wo     = (const float*)d_in[6];
    const float* bo     = (const float*)d_in[7];
    float* out = (float*)d_out;

    float *q, *xkt, *xvt, *projkt, *projvt, *keys2, *vals2, *ctx;
    cudaGetSymbolAddress((void**)&q,      g_q);
    cudaGetSymbolAddress((void**)&xkt,    g_xkt);
    cudaGetSymbolAddress((void**)&xvt,    g_xvt);
    cudaGetSymbolAddress((void**)&projkt, g_projkt);
    cudaGetSymbolAddress((void**)&projvt, g_projvt);
    cudaGetSymbolAddress((void**)&keys2,  g_keys2);
    cudaGetSymbolAddress((void**)&vals2,  g_vals2);
    cudaGetSymbolAddress((void**)&ctx,    g_ctx);

    cudaFuncSetAttribute(gemm3,          cudaFuncAttributeMaxDynamicSharedMemorySize, GEMM64_SMEM);
    cudaFuncSetAttribute(gemm_big<true>, cudaFuncAttributeMaxDynamicSharedMemorySize, GEMM64_SMEM);
    cudaFuncSetAttribute(gemm_ws,        cudaFuncAttributeMaxDynamicSharedMemorySize, GEMM_SMEM);
    cudaFuncSetAttribute(attn_mma,       cudaFuncAttributeMaxDynamicSharedMemorySize, ATTN_SMEM);

    // proj_k / proj_v -> transposed [K,L]
    transpose_proj<<<dim3(KK/32, LL/32, 2), dim3(32, 8)>>>(proj_k, proj_v, projkt, projvt);

    // q + xkt + xvt merged (1536 CTAs, one wave-tail)
    gemm3<<<1536, 384, GEMM64_SMEM>>>(x, Wq, Wk, Wv, q, xkt, xvt);

    // keys2/vals2 partials merged
    gemm_ws<<<dim3(DD/128, KK/128, 2*BB*2), 384, GEMM_SMEM>>>(
        projkt, projvt, 0, LL,
        xkt, xvt, (long)DD*LL, LL,
        keys2, vals2, (long)KK*DD, (long)BB*KK*DD, DD,
        LL/2, 2, BB*2);

    // MMA attention (online softmax, 2-chunk; fuses the split-K adds)
    attn_mma<<<dim3(LL/128, HH, BB), 256, ATTN_SMEM>>>();

    // out = ctx @ Wo^T + bo
    gemm_big<true><<<dim3(DD/128, MROWS/128, 1), 384, GEMM64_SMEM>>>(
        ctx, 0, DD, Wo, 0, DD, out, 0, DD, bo, DD);
}

// round 16
// speedup vs baseline: 1.0391x; 1.0391x over previous
#include <cuda_runtime.h>
#include <cuda_fp16.h>
#include <cstdint>
#include <math.h>

#define BB 4
#define LL 2048
#define DD 1024
#define HH 16
#define KK 256
#define DH 64
#define MROWS (BB*LL)   // 8192

// ---- scratch (device globals; no runtime allocation allowed) ----
__device__ float g_q[BB*LL*DD];        // x @ Wq^T            [B,L,D]
__device__ float g_xkt[BB*DD*LL];      // (x @ Wk^T)^T        [B,D,L]
__device__ float g_xvt[BB*DD*LL];      // (x @ Wv^T)^T        [B,D,L]
__device__ float g_projkt[KK*LL];      // proj_k^T            [K,L]
__device__ float g_projvt[KK*LL];      // proj_v^T            [K,L]
__device__ float g_keys[BB*KK*DD];     // keys [B,K,D]
__device__ float g_vals[BB*KK*DD];     // vals [B,K,D]
__device__ float g_ctx[BB*LL*DD];      // attention out       [B,L,D]

// ============================================================
// helpers
// ============================================================
__device__ __forceinline__ uint32_t smem_u32(const void* p) {
    uint32_t a;
    asm("{ .reg .u64 t; cvta.to.shared.u64 t, %1; cvt.u32.u64 %0, t; }"
        : "=r"(a) : "l"(p));
    return a;
}
__device__ __forceinline__ void ldsm4(uint32_t* r, uint32_t addr) {
    asm volatile("ldmatrix.sync.aligned.m8n8.x4.shared.b16 {%0,%1,%2,%3}, [%4];"
        : "=r"(r[0]), "=r"(r[1]), "=r"(r[2]), "=r"(r[3]) : "r"(addr));
}
__device__ __forceinline__ void ldsm2(uint32_t* r, uint32_t addr) {
    asm volatile("ldmatrix.sync.aligned.m8n8.x2.shared.b16 {%0,%1}, [%2];"
        : "=r"(r[0]), "=r"(r[1]) : "r"(addr));
}
__device__ __forceinline__ void ldsm2t(uint32_t* r, uint32_t addr) {
    asm volatile("ldmatrix.sync.aligned.m8n8.x2.trans.shared.b16 {%0,%1}, [%2];"
        : "=r"(r[0]), "=r"(r[1]) : "r"(addr));
}
__device__ __forceinline__ void mma16816(float* c, const uint32_t* a, const uint32_t* b) {
    asm volatile(
        "mma.sync.aligned.m16n8k16.row.col.f32.f16.f16.f32 "
        "{%0,%1,%2,%3}, {%4,%5,%6,%7}, {%8,%9}, {%0,%1,%2,%3};"
        : "+f"(c[0]), "+f"(c[1]), "+f"(c[2]), "+f"(c[3])
        : "r"(a[0]), "r"(a[1]), "r"(a[2]), "r"(a[3]), "r"(b[0]), "r"(b[1]));
}
#define BAR_SYNC(id)   asm volatile("bar.sync %0, 384;"   :: "r"(id) : "memory")
#define BAR_ARRIVE(id) asm volatile("bar.arrive %0, 384;" :: "r"(id) : "memory")

// split 8 f32 -> 16B hi chunk + 16B lo chunk
__device__ __forceinline__ void cvt_split16(float4 a, float4 b, uint4& hi, uint4& lo) {
    __half2 h0 = __floats2half2_rn(a.x, a.y);
    __half2 h1 = __floats2half2_rn(a.z, a.w);
    __half2 h2 = __floats2half2_rn(b.x, b.y);
    __half2 h3 = __floats2half2_rn(b.z, b.w);
    float2 f0 = __half22float2(h0);
    float2 f1 = __half22float2(h1);
    float2 f2 = __half22float2(h2);
    float2 f3 = __half22float2(h3);
    __half2 l0 = __floats2half2_rn(a.x - f0.x, a.y - f0.y);
    __half2 l1 = __floats2half2_rn(a.z - f1.x, a.w - f1.y);
    __half2 l2 = __floats2half2_rn(b.x - f2.x, b.y - f2.y);
    __half2 l3 = __floats2half2_rn(b.z - f3.x, b.w - f3.y);
    hi.x = *(uint32_t*)&h0; hi.y = *(uint32_t*)&h1;
    hi.z = *(uint32_t*)&h2; hi.w = *(uint32_t*)&h3;
    lo.x = *(uint32_t*)&l0; lo.y = *(uint32_t*)&l1;
    lo.z = *(uint32_t*)&l2; lo.w = *(uint32_t*)&l3;
}
// round 8 f32 -> 16B fp16 chunk (hi only)
__device__ __forceinline__ void cvt_hi16(float4 a, float4 b, uint4& hi) {
    __half2 h0 = __floats2half2_rn(a.x, a.y);
    __half2 h1 = __floats2half2_rn(a.z, a.w);
    __half2 h2 = __floats2half2_rn(b.x, b.y);
    __half2 h3 = __floats2half2_rn(b.z, b.w);
    hi.x = *(uint32_t*)&h0; hi.y = *(uint32_t*)&h1;
    hi.z = *(uint32_t*)&h2; hi.w = *(uint32_t*)&h3;
}

// ============================================================
// Shared GEMM body constants (BK=64, 2-stage, 128x128 tile)
// ============================================================
#define T64B 16384                    // one plane: 128 rows x 128B
#define STG64B (3*T64B)               // A_hi, B_hi, B_lo = 49152
#define GEMM64_SMEM (2*STG64B)        // 98304

// ---- producer body (shared by gemm_big / gemm3) ----
__device__ __forceinline__ void big_producer(
    char* smc, const float* A, const float* B, int lda, int ldb,
    int m0, int n0, int iters, int tid)
{
    const int ptid = tid - 256;
    const float* Aip = A + (size_t)m0 * lda;
    const float* Bip = B + (size_t)n0 * ldb;

    for (int it = 0; it < iters; it++) {
        const int s = it & 1;
        if (it >= 2) BAR_SYNC(4 + s);             // EMPTY(s)
        const int k0 = it * 64;
        char* stg = smc + s * STG64B;
        #pragma unroll
        for (int p = 0; p < 8; p++) {
            int idx = ptid + p * 128;             // 0..1023
            int r = idx >> 3, c = idx & 7;
            int sw = r * 128 + ((c ^ (r & 7)) << 4);
            const float* src = Aip + (size_t)r * lda + k0 + c * 8;
            float4 v0 = *(const float4*)src;
            float4 v1 = *(const float4*)(src + 4);
            uint4 hi;
            cvt_hi16(v0, v1, hi);
            *(uint4*)(stg + sw) = hi;
        }
        #pragma unroll
        for (int p = 0; p < 8; p++) {
            int idx = ptid + p * 128;
            int r = idx >> 3, c = idx & 7;
            int sw = r * 128 + ((c ^ (r & 7)) << 4);
            const float* src = Bip + (size_t)r * ldb + k0 + c * 8;
            float4 v0 = *(const float4*)src;
            float4 v1 = *(const float4*)(src + 4);
            uint4 hi, lo;
            cvt_split16(v0, v1, hi, lo);
            *(uint4*)(stg + T64B + sw) = hi;
            *(uint4*)(stg + 2*T64B + sw) = lo;
        }
        BAR_ARRIVE(1 + s);                        // FULL(s)
    }
}

// ---- consumer body (software-pipelined fragments) ----
template<bool BIAS>
__device__ __forceinline__ void big_consumer(
    char* smc, float* C, int ldc, const float* bias,
    int m0, int n0, int iters, int tid)
{
    const int lane = tid & 31;
    const int wid  = tid >> 5;
    const int wm = wid >> 2;
    const int wn = wid & 3;
    const int g  = lane >> 2;
    const int tig = lane & 3;
    const uint32_t sbase = smem_u32(smc);
    const int grp = lane >> 3;
    const int bt  = lane & 7;

    float acc[4][4][4];
    #pragma unroll
    for (int i = 0; i < 4; i++)
        #pragma unroll
        for (int j = 0; j < 4; j++)
            #pragma unroll
            for (int v = 0; v < 4; v++) acc[i][j][v] = 0.f;

    uint32_t ah[2][4][4], bh[2][4][2], bl[2][4][2];

    auto load_frags = [&](uint32_t stg, int kt, int buf) {
        const int cA = kt * 2 + (lane >> 4);
        #pragma unroll
        for (int mi = 0; mi < 4; mi++) {
            int r = wm * 64 + mi * 16 + (lane & 15);
            uint32_t off = (uint32_t)(r * 128 + ((cA ^ (r & 7)) << 4));
            ldsm4(ah[buf][mi], stg + off);
        }
        #pragma unroll
        for (int nip = 0; nip < 2; nip++) {
            int row = wn * 32 + nip * 16 + ((grp >> 1) << 3) + bt;
            int cc  = kt * 2 + (grp & 1);
            uint32_t off = (uint32_t)(row * 128 + ((cc ^ (row & 7)) << 4));
            uint32_t r4[4];
            ldsm4(r4, stg + T64B + off);
            bh[buf][nip*2][0]   = r4[0]; bh[buf][nip*2][1]   = r4[1];
            bh[buf][nip*2+1][0] = r4[2]; bh[buf][nip*2+1][1] = r4[3];
            ldsm4(r4, stg + 2*T64B + off);
            bl[buf][nip*2][0]   = r4[0]; bl[buf][nip*2][1]   = r4[1];
            bl[buf][nip*2+1][0] = r4[2]; bl[buf][nip*2+1][1] = r4[3];
        }
    };

    for (int it = 0; it < iters; it++) {
        const int s = it & 1;
        BAR_SYNC(1 + s);                          // FULL(s)
        const uint32_t stg = sbase + s * STG64B;

        load_frags(stg, 0, 0);
        #pragma unroll
        for (int kt = 0; kt < 4; kt++) {
            const int cur = kt & 1;
            if (kt < 3) load_frags(stg, kt + 1, cur ^ 1);
            #pragma unroll
            for (int mi = 0; mi < 4; mi++)
                #pragma unroll
                for (int ni = 0; ni < 4; ni++) {
                    mma16816(acc[mi][ni], ah[cur][mi], bh[cur][ni]);
                    mma16816(acc[mi][ni], ah[cur][mi], bl[cur][ni]);
                }
        }
        BAR_ARRIVE(4 + s);                        // EMPTY(s)
    }

    #pragma unroll
    for (int mi = 0; mi < 4; mi++) {
        const int r0 = m0 + wm * 64 + mi * 16 + g;
        #pragma unroll
        for (int ni = 0; ni < 4; ni++) {
            const int col = n0 + wn * 32 + ni * 8 + tig * 2;
            float2 v0, v1;
            v0.x = acc[mi][ni][0]; v0.y = acc[mi][ni][1];
            v1.x = acc[mi][ni][2]; v1.y = acc[mi][ni][3];
            if (BIAS) {
                float2 bv = *(const float2*)(bias + col);
                v0.x += bv.x; v0.y += bv.y;
                v1.x += bv.x; v1.y += bv.y;
            }
            *(float2*)(C + (size_t)r0 * ldc + col) = v0;
            *(float2*)(C + (size_t)(r0 + 8) * ldc + col) = v1;
        }
    }
}

// ============================================================
// gemm_big: single-problem BK=64 GEMM (used for out-GEMM)
// ============================================================
template<bool BIAS>
__global__ __launch_bounds__(384, 1)
void gemm_big(const float* __restrict__ A, long Ab, int lda,
              const float* __restrict__ B, long Bb, int ldb,
              float* __restrict__ C, long Cb, int ldc,
              const float* __restrict__ bias, int Kd)
{
    extern __shared__ __align__(16) char smc[];
    const int tid = threadIdx.x;
    const int z = blockIdx.z;
    const float* Ap = A + (size_t)z * Ab;
    const float* Bp = B + (size_t)z * Bb;
    float* Cp = C + (size_t)z * Cb;
    const int m0 = blockIdx.y * 128;
    const int n0 = blockIdx.x * 128;
    const int iters = Kd / 64;

    if ((tid >> 5) >= 8) big_producer(smc, Ap, Bp, lda, ldb, m0, n0, iters, tid);
    else big_consumer<BIAS>(smc, Cp, ldc, bias, m0, n0, iters, tid);
}

// ============================================================
// gemm3: q + xkt + xvt merged (1536 CTAs, flattened 1D grid)
// ============================================================
__global__ __launch_bounds__(384, 1)
void gemm3(const float* __restrict__ x,
           const float* __restrict__ Wq,
           const float* __restrict__ Wk,
           const float* __restrict__ Wv,
           float* __restrict__ q,
           float* __restrict__ xkt,
           float* __restrict__ xvt)
{
    extern __shared__ __align__(16) char smc[];
    const int tid = threadIdx.x;
    int t = blockIdx.x;

    const float *A, *B;
    float* C;
    int m0, n0, ldb, ldc;
    if (t < 512) {
        A = x; B = Wq; C = q;
        m0 = (t >> 3) * 128; n0 = (t & 7) * 128;
        ldb = DD; ldc = DD;
    } else {
        int which = (t >= 1024);
        int u = t - (which ? 1024 : 512);
        int b = u >> 7;
        int rem = u & 127;
        A = which ? Wv : Wk;
        B = x + (size_t)b * LL * DD;
        C = (which ? xvt : xkt) + (size_t)b * DD * LL;
        m0 = (rem >> 4) * 128; n0 = (rem & 15) * 128;
        ldb = DD; ldc = LL;
    }

    if ((tid >> 5) >= 8) big_producer(smc, A, B, DD, ldb, m0, n0, DD / 64, tid);
    else big_consumer<false>(smc, C, ldc, nullptr, m0, n0, DD / 64, tid);
}

// ============================================================
// 128x128 BK=32 warp-specialized 2-MMA split GEMM (proj GEMMs, merged,
// NO split-K: full L=2048 reduction per CTA; 128 CTAs total)
// z in [0,8): which = z>=4 (K vs V), b = z&3
// ============================================================
#define TILEB 8192
#define STGB  (3*TILEB)
#define NSTG  3
#define GEMM_SMEM (NSTG*STGB)        // 73728

__global__ __launch_bounds__(384, 1)
void gemm_ws(const float* __restrict__ A0, const float* __restrict__ A1,
             const float* __restrict__ B0, const float* __restrict__ B1,
             float* __restrict__ C0, float* __restrict__ C1,
             int Kd, int zhalf)
{
    extern __shared__ __align__(16) char smc[];

    const int tid  = threadIdx.x;
    const int lane = tid & 31;
    const int wid  = tid >> 5;

    int z = blockIdx.z;
    const float* A = A0;
    const float* B = B0;
    float* C = C0;
    if (z >= zhalf) { A = A1; B = B1; C = C1; z -= zhalf; }
    B += (size_t)z * DD * LL;
    C += (size_t)z * KK * DD;
    const int m0 = blockIdx.y * 128;
    const int n0 = blockIdx.x * 128;
    const int iters = Kd / 32;

    if (wid >= 8) {
        const int ptid = tid - 256;
        const float* Aip = A + (size_t)m0 * LL;
        const float* Bip = B + (size_t)n0 * LL;

        for (int it = 0; it < iters; it++) {
            const int s = it % NSTG;
            if (it >= NSTG) BAR_SYNC(4 + s);
            const int k0 = it * 32;
            char* stg = smc + s * STGB;
            #pragma unroll
            for (int p = 0; p < 4; p++) {
                int idx = ptid + p * 128;
                int r = idx >> 2, c = idx & 3;
                int sw = (c ^ ((r >> 1) & 3)) * 16;
                {
                    const float* src = Aip + (size_t)r * LL + k0 + c * 8;
                    float4 v0 = *(const float4*)src;
                    float4 v1 = *(const float4*)(src + 4);
                    uint4 hi;
                    cvt_hi16(v0, v1, hi);
                    *(uint4*)(stg + r * 64 + sw) = hi;
                }
                {
                    const float* src = Bip + (size_t)r * LL + k0 + c * 8;
                    float4 v0 = *(const float4*)src;
                    float4 v1 = *(const float4*)(src + 4);
                    uint4 hi, lo;
                    cvt_split16(v0, v1, hi, lo);
                    *(uint4*)(stg + TILEB + r * 64 + sw) = hi;
                    *(uint4*)(stg + 2*TILEB + r * 64 + sw) = lo;
                }
            }
            BAR_ARRIVE(1 + s);
        }
    } else {
        const int wm = wid >> 2;
        const int wn = wid & 3;
        const int g  = lane >> 2;
        const int tig = lane & 3;
        const uint32_t sbase = smem_u32(smc);

        float acc[4][4][4];
        #pragma unroll
        for (int i = 0; i < 4; i++)
            #pragma unroll
            for (int j = 0; j < 4; j++)
                #pragma unroll
                for (int v = 0; v < 4; v++) acc[i][j][v] = 0.f;

        for (int it = 0; it < iters; it++) {
            const int s = it % NSTG;
            BAR_SYNC(1 + s);
            const uint32_t stg = sbase + s * STGB;

            uint32_t ah[2][4][4], bh[2][4][2], bl[2][4][2];
            #pragma unroll
            for (int ks = 0; ks < 2; ks++) {
                const int cA = ks * 2 + (lane >> 4);
                #pragma unroll
                for (int mi = 0; mi < 4; mi++) {
                    int r = wm * 64 + mi * 16 + (lane & 15);
                    uint32_t off = (uint32_t)(r * 64 + ((cA ^ ((r >> 1) & 3)) << 4));
                    ldsm4(ah[ks][mi], stg + off);
                }
                const int cB = ks * 2 + ((lane >> 3) & 1);
                #pragma unroll
                for (int ni = 0; ni < 4; ni++) {
                    int r = wn * 32 + ni * 8 + (lane & 7);
                    uint32_t off = (uint32_t)(r * 64 + ((cB ^ ((r >> 1) & 3)) << 4));
                    ldsm2(bh[ks][ni], stg + TILEB + off);
                    ldsm2(bl[ks][ni], stg + 2*TILEB + off);
                }
            }
            #pragma unroll
            for (int ks = 0; ks < 2; ks++)
                #pragma unroll
                for (int mi = 0; mi < 4; mi++)
                    #pragma unroll
                    for (int ni = 0; ni < 4; ni++) {
                        mma16816(acc[mi][ni], ah[ks][mi], bh[ks][ni]);
                        mma16816(acc[mi][ni], ah[ks][mi], bl[ks][ni]);
                    }
            BAR_ARRIVE(4 + s);
        }

        #pragma unroll
        for (int mi = 0; mi < 4; mi++) {
            const int r0 = m0 + wm * 64 + mi * 16 + g;
            #pragma unroll
            for (int ni = 0; ni < 4; ni++) {
                const int col = n0 + wn * 32 + ni * 8 + tig * 2;
                float2 v0, v1;
                v0.x = acc[mi][ni][0]; v0.y = acc[mi][ni][1];
                v1.x = acc[mi][ni][2]; v1.y = acc[mi][ni][3];
                *(float2*)(C + (size_t)r0 * DD + col) = v0;
                *(float2*)(C + (size_t)(r0 + 8) * DD + col) = v1;
            }
        }
    }
}

// ============================================================
// proj transpose: [L,K] -> [K,L]
// ============================================================
__global__ __launch_bounds__(256)
void transpose_proj(const float* __restrict__ pk, const float* __restrict__ pv,
                    float* __restrict__ okt, float* __restrict__ ovt)
{
    __shared__ float t[32][33];
    const float* src = blockIdx.z ? pv : pk;
    float* dst       = blockIdx.z ? ovt : okt;
    int k0 = blockIdx.x * 32, l0 = blockIdx.y * 32;
    int tx = threadIdx.x, ty = threadIdx.y;
    #pragma unroll
    for (int i = 0; i < 32; i += 8)
        t[ty + i][tx] = src[(size_t)(l0 + ty + i) * KK + k0 + tx];
    __syncthreads();
    #pragma unroll
    for (int i = 0; i < 32; i += 8)
        dst[(size_t)(k0 + ty + i) * LL + l0 + tx] = t[tx][ty + i];
}

// ============================================================
// MMA attention (R14-proven): monolithic acc, 2-MMA split both phases.
// Reads final keys/vals (no split-K partials).
// ============================================================
#define AQH 0
#define AKH 16384
#define AKL 49152
#define AVH 81920
#define AVL 114688
#define ATTN_SMEM 147456

__global__ __launch_bounds__(256, 1)
void attn_mma()
{
    extern __shared__ __align__(16) char smc[];
    const uint32_t base = smem_u32(smc);

    const int b  = blockIdx.z;
    const int h  = blockIdx.y;
    const int l0 = blockIdx.x * 128;
    const int tid  = threadIdx.x;
    const int lane = tid & 31;
    const int wy   = tid >> 5;
    const int g    = lane >> 2;
    const int tig  = lane & 3;

    // ---- fill Q (hi only) ----
    #pragma unroll
    for (int it = 0; it < 4; it++) {
        int idx = tid + it * 256;
        int r = idx >> 3, c = idx & 7;
        int l = l0 + r;
        const float* src = g_q + ((size_t)(b * LL) + h * 128 + (l >> 4)) * DD
                               + (l & 15) * DH + c * 8;
        float4 v0 = *(const float4*)src;
        float4 v1 = *(const float4*)(src + 4);
        uint4 hi;
        cvt_hi16(v0, v1, hi);
        int sw = r * 128 + ((c ^ (r & 7)) << 4);
        *(uint4*)(smc + AQH + sw) = hi;
    }
    // ---- fill K (hi/lo) ----
    #pragma unroll
    for (int it = 0; it < 8; it++) {
        int idx = tid + it * 256;
        int r = idx >> 3, c = idx & 7;
        size_t o = ((size_t)b * KK + r) * DD + h * DH + c * 8;
        float4 a0 = *(const float4*)&g_keys[o];
        float4 a1 = *(const float4*)&g_keys[o + 4];
        uint4 hi, lo;
        cvt_split16(a0, a1, hi, lo);
        int sw = r * 128 + ((c ^ (r & 7)) << 4);
        *(uint4*)(smc + AKH + sw) = hi;
        *(uint4*)(smc + AKL + sw) = lo;
    }
    // ---- fill V (hi/lo) ----
    #pragma unroll
    for (int it = 0; it < 8; it++) {
        int idx = tid + it * 256;
        int r = idx >> 3, c = idx & 7;
        size_t o = ((size_t)b * KK + r) * DD + h * DH + c * 8;
        float4 a0 = *(const float4*)&g_vals[o];
        float4 a1 = *(const float4*)&g_vals[o + 4];
        uint4 hi, lo;
        cvt_split16(a0, a1, hi, lo);
        int sw = r * 128 + ((c ^ (r & 7)) << 4);
        *(uint4*)(smc + AVH + sw) = hi;
        *(uint4*)(smc + AVL + sw) = lo;
    }
    __syncthreads();

    const int m0w = wy * 16;

    // ---- Q A-fragments (hi only) ----
    uint32_t qa_h[4][4];
    {
        int r = m0w + (lane & 15);
        #pragma unroll
        for (int kt = 0; kt < 4; kt++) {
            int c = kt * 2 + (lane >> 4);
            uint32_t off = (uint32_t)(r * 128 + ((c ^ (r & 7)) << 4));
            ldsm4(qa_h[kt], base + AQH + off);
        }
    }

    // ---- S = Qh Kh^T + Qh Kl^T ----
    float acc[32][4];
    #pragma unroll
    for (int nt = 0; nt < 32; nt++)
        #pragma unroll
        for (int v = 0; v < 4; v++) acc[nt][v] = 0.f;

    #pragma unroll
    for (int nt = 0; nt < 32; nt++) {
        int r = nt * 8 + (lane & 7);
        int c0 = (lane >> 3);
        uint32_t off1 = (uint32_t)(r * 128 + ((c0 ^ (r & 7)) << 4));
        uint32_t off2 = (uint32_t)(r * 128 + (((c0 + 4) ^ (r & 7)) << 4));
        uint32_t kh[8], kl[8];
        ldsm4(kh,     base + AKH + off1);
        ldsm4(kh + 4, base + AKH + off2);
        ldsm4(kl,     base + AKL + off1);
        ldsm4(kl + 4, base + AKL + off2);
        #pragma unroll
        for (int kt = 0; kt < 4; kt++) {
            mma16816(acc[nt], qa_h[kt], kh + kt * 2);
            mma16816(acc[nt], qa_h[kt], kl + kt * 2);
        }
    }

    // ---- softmax (rows g and g+8) ----
    const float SC = 0.125f;
    float mx0 = -1e30f, mx1 = -1e30f;
    #pragma unroll
    for (int nt = 0; nt < 32; nt++) {
        mx0 = fmaxf(mx0, fmaxf(acc[nt][0], acc[nt][1]));
        mx1 = fmaxf(mx1, fmaxf(acc[nt][2], acc[nt][3]));
    }
    #pragma unroll
    for (int o = 1; o <= 2; o <<= 1) {
        mx0 = fmaxf(mx0, __shfl_xor_sync(0xffffffffu, mx0, o));
        mx1 = fmaxf(mx1, __shfl_xor_sync(0xffffffffu, mx1, o));
    }
    const float b0s = mx0 * SC, b1s = mx1 * SC;
    float s0 = 0.f, s1 = 0.f;
    #pragma unroll
    for (int nt = 0; nt < 32; nt++) {
        acc[nt][0] = __expf(acc[nt][0] * SC - b0s);
        acc[nt][1] = __expf(acc[nt][1] * SC - b0s);
        acc[nt][2] = __expf(acc[nt][2] * SC - b1s);
        acc[nt][3] = __expf(acc[nt][3] * SC - b1s);
        s0 += acc[nt][0] + acc[nt][1];
        s1 += acc[nt][2] + acc[nt][3];
    }
    #pragma unroll
    for (int o = 1; o <= 2; o <<= 1) {
        s0 += __shfl_xor_sync(0xffffffffu, s0, o);
        s1 += __shfl_xor_sync(0xffffffffu, s1, o);
    }
    const float inv0 = 1.f / s0, inv1 = 1.f / s1;

    // ---- O = Ph Vh + Ph Vl ----
    float oac[8][4];
    #pragma unroll
    for (int nj = 0; nj < 8; nj++)
        #pragma unroll
        for (int v = 0; v < 4; v++) oac[nj][v] = 0.f;

    #pragma unroll
    for (int kt = 0; kt < 16; kt++) {
        uint32_t ph[4];
        #pragma unroll
        for (int half_ = 0; half_ < 2; half_++) {
            const float* c = acc[2 * kt + half_];
            __half2 h0 = __floats2half2_rn(c[0], c[1]);
            __half2 h1 = __floats2half2_rn(c[2], c[3]);
            ph[half_ * 2 + 0] = *(uint32_t*)&h0;
            ph[half_ * 2 + 1] = *(uint32_t*)&h1;
        }
        int rv = kt * 16 + (lane & 15);
        #pragma unroll
        for (int nj = 0; nj < 8; nj++) {
            uint32_t off = (uint32_t)(rv * 128 + ((nj ^ (rv & 7)) << 4));
            uint32_t vh[2], vl[2];
            ldsm2t(vh, base + AVH + off);
            ldsm2t(vl, base + AVL + off);
            mma16816(oac[nj], ph, vh);
            mma16816(oac[nj], ph, vl);
        }
    }

    {
        const int r0 = l0 + m0w + g;
        const size_t orow = ((size_t)(b * LL) + r0) * DD + h * DH;
        #pragma unroll
        for (int nj = 0; nj < 8; nj++) {
            float2 v0, v1;
            v0.x = oac[nj][0] * inv0; v0.y = oac[nj][1] * inv0;
            v1.x = oac[nj][2] * inv1; v1.y = oac[nj][3] * inv1;
            *(float2*)&g_ctx[orow + nj * 8 + tig * 2] = v0;
            *(float2*)&g_ctx[orow + (size_t)8 * DD + nj * 8 + tig * 2] = v1;
        }
    }
}

// ============================================================
extern "C" void kernel_launch(void* const* d_in, const int* in_sizes, int n_in,
                              void* d_out, int out_size)
{
    const float* x      = (const float*)d_in[0];
    const float* Wq     = (const float*)d_in[1];
    const float* Wk     = (const float*)d_in[2];
    const float* Wv     = (const float*)d_in[3];
    const float* proj_k = (const float*)d_in[4];
    const float* proj_v = (const float*)d_in[5];
    const float* Wo     = (const float*)d_in[6];
    const float* bo     = (const float*)d_in[7];
    float* out = (float*)d_out;

    float *q, *xkt, *xvt, *projkt, *projvt, *keys, *vals, *ctx;
    cudaGetSymbolAddress((void**)&q,      g_q);
    cudaGetSymbolAddress((void**)&xkt,    g_xkt);
    cudaGetSymbolAddress((void**)&xvt,    g_xvt);
    cudaGetSymbolAddress((void**)&projkt, g_projkt);
    cudaGetSymbolAddress((void**)&projvt, g_projvt);
    cudaGetSymbolAddress((void**)&keys,   g_keys);
    cudaGetSymbolAddress((void**)&vals,   g_vals);
    cudaGetSymbolAddress((void**)&ctx,    g_ctx);

    cudaFuncSetAttribute(gemm3,          cudaFuncAttributeMaxDynamicSharedMemorySize, GEMM64_SMEM);
    cudaFuncSetAttribute(gemm_big<true>, cudaFuncAttributeMaxDynamicSharedMemorySize, GEMM64_SMEM);
    cudaFuncSetAttribute(gemm_ws,        cudaFuncAttributeMaxDynamicSharedMemorySize, GEMM_SMEM);
    cudaFuncSetAttribute(attn_mma,       cudaFuncAttributeMaxDynamicSharedMemorySize, ATTN_SMEM);

    // proj_k / proj_v -> transposed [K,L]
    transpose_proj<<<dim3(KK/32, LL/32, 2), dim3(32, 8)>>>(proj_k, proj_v, projkt, projvt);

    // q + xkt + xvt merged (1536 CTAs, one wave-tail)
    gemm3<<<1536, 384, GEMM64_SMEM>>>(x, Wq, Wk, Wv, q, xkt, xvt);

    // keys/vals merged, NO split-K (128 CTAs, full L reduction per CTA):
    // keys[b][K,D] = projkt x xkt_b^T ; vals[b][K,D] = projvt x xvt_b^T
    gemm_ws<<<dim3(DD/128, KK/128, 2*BB), 384, GEMM_SMEM>>>(
        projkt, projvt, xkt, xvt, keys, vals, LL, BB);

    // MMA attention (monolithic, 2-MMA split)
    attn_mma<<<dim3(LL/128, HH, BB), 256, ATTN_SMEM>>>();

    // out = ctx @ Wo^T + bo
    gemm_big<true><<<dim3(DD/128, MROWS/128, 1), 384, GEMM64_SMEM>>>(
        ctx, 0, DD, Wo, 0, DD, out, 0, DD, bo, DD);
}

// round 17
// speedup vs baseline: 1.0397x; 1.0006x over previous
#include <cuda_runtime.h>
#include <cuda_fp16.h>
#include <cstdint>
#include <math.h>

#define BB 4
#define LL 2048
#define DD 1024
#define HH 16
#define KK 256
#define DH 64
#define MROWS (BB*LL)   // 8192

// ---- scratch (device globals; no runtime allocation allowed) ----
__device__ float g_q[BB*LL*DD];        // x @ Wq^T            [B,L,D]
__device__ float g_xkt[BB*DD*LL];      // (x @ Wk^T)^T        [B,D,L]
__device__ float g_xvt[BB*DD*LL];      // (x @ Wv^T)^T        [B,D,L]
__device__ float g_projkt[KK*LL];      // proj_k^T            [K,L]
__device__ float g_projvt[KK*LL];      // proj_v^T            [K,L]
__device__ float g_keys[BB*KK*DD];     // keys [B,K,D]
__device__ float g_vals[BB*KK*DD];     // vals [B,K,D]
__device__ float g_ctx[BB*LL*DD];      // attention out       [B,L,D]

// ============================================================
// helpers
// ============================================================
__device__ __forceinline__ uint32_t smem_u32(const void* p) {
    uint32_t a;
    asm("{ .reg .u64 t; cvta.to.shared.u64 t, %1; cvt.u32.u64 %0, t; }"
        : "=r"(a) : "l"(p));
    return a;
}
__device__ __forceinline__ void ldsm4(uint32_t* r, uint32_t addr) {
    asm volatile("ldmatrix.sync.aligned.m8n8.x4.shared.b16 {%0,%1,%2,%3}, [%4];"
        : "=r"(r[0]), "=r"(r[1]), "=r"(r[2]), "=r"(r[3]) : "r"(addr));
}
__device__ __forceinline__ void ldsm2(uint32_t* r, uint32_t addr) {
    asm volatile("ldmatrix.sync.aligned.m8n8.x2.shared.b16 {%0,%1}, [%2];"
        : "=r"(r[0]), "=r"(r[1]) : "r"(addr));
}
__device__ __forceinline__ void ldsm2t(uint32_t* r, uint32_t addr) {
    asm volatile("ldmatrix.sync.aligned.m8n8.x2.trans.shared.b16 {%0,%1}, [%2];"
        : "=r"(r[0]), "=r"(r[1]) : "r"(addr));
}
__device__ __forceinline__ void mma16816(float* c, const uint32_t* a, const uint32_t* b) {
    asm volatile(
        "mma.sync.aligned.m16n8k16.row.col.f32.f16.f16.f32 "
        "{%0,%1,%2,%3}, {%4,%5,%6,%7}, {%8,%9}, {%0,%1,%2,%3};"
        : "+f"(c[0]), "+f"(c[1]), "+f"(c[2]), "+f"(c[3])
        : "r"(a[0]), "r"(a[1]), "r"(a[2]), "r"(a[3]), "r"(b[0]), "r"(b[1]));
}
#define BAR_SYNC(id)   asm volatile("bar.sync %0, 384;"   :: "r"(id) : "memory")
#define BAR_ARRIVE(id) asm volatile("bar.arrive %0, 384;" :: "r"(id) : "memory")

// split 8 f32 -> 16B hi chunk + 16B lo chunk
__device__ __forceinline__ void cvt_split16(float4 a, float4 b, uint4& hi, uint4& lo) {
    __half2 h0 = __floats2half2_rn(a.x, a.y);
    __half2 h1 = __floats2half2_rn(a.z, a.w);
    __half2 h2 = __floats2half2_rn(b.x, b.y);
    __half2 h3 = __floats2half2_rn(b.z, b.w);
    float2 f0 = __half22float2(h0);
    float2 f1 = __half22float2(h1);
    float2 f2 = __half22float2(h2);
    float2 f3 = __half22float2(h3);
    __half2 l0 = __floats2half2_rn(a.x - f0.x, a.y - f0.y);
    __half2 l1 = __floats2half2_rn(a.z - f1.x, a.w - f1.y);
    __half2 l2 = __floats2half2_rn(b.x - f2.x, b.y - f2.y);
    __half2 l3 = __floats2half2_rn(b.z - f3.x, b.w - f3.y);
    hi.x = *(uint32_t*)&h0; hi.y = *(uint32_t*)&h1;
    hi.z = *(uint32_t*)&h2; hi.w = *(uint32_t*)&h3;
    lo.x = *(uint32_t*)&l0; lo.y = *(uint32_t*)&l1;
    lo.z = *(uint32_t*)&l2; lo.w = *(uint32_t*)&l3;
}
// round 8 f32 -> 16B fp16 chunk (hi only)
__device__ __forceinline__ void cvt_hi16(float4 a, float4 b, uint4& hi) {
    __half2 h0 = __floats2half2_rn(a.x, a.y);
    __half2 h1 = __floats2half2_rn(a.z, a.w);
    __half2 h2 = __floats2half2_rn(b.x, b.y);
    __half2 h3 = __floats2half2_rn(b.z, b.w);
    hi.x = *(uint32_t*)&h0; hi.y = *(uint32_t*)&h1;
    hi.z = *(uint32_t*)&h2; hi.w = *(uint32_t*)&h3;
}

// ============================================================
// Shared GEMM body constants (BK=64, 2-stage, 128x128 tile)
// ============================================================
#define T64B 16384                    // one plane: 128 rows x 128B
#define STG64B (3*T64B)               // A_hi, B_hi, B_lo = 49152
#define GEMM64_SMEM (2*STG64B)        // 98304

// ---- producer body (shared by gemm_big / gemm3) ----
__device__ __forceinline__ void big_producer(
    char* smc, const float* A, const float* B, int lda, int ldb,
    int m0, int n0, int iters, int tid)
{
    const int ptid = tid - 256;
    const float* Aip = A + (size_t)m0 * lda;
    const float* Bip = B + (size_t)n0 * ldb;

    for (int it = 0; it < iters; it++) {
        const int s = it & 1;
        if (it >= 2) BAR_SYNC(4 + s);             // EMPTY(s)
        const int k0 = it * 64;
        char* stg = smc + s * STG64B;
        #pragma unroll
        for (int p = 0; p < 8; p++) {
            int idx = ptid + p * 128;             // 0..1023
            int r = idx >> 3, c = idx & 7;
            int sw = r * 128 + ((c ^ (r & 7)) << 4);
            const float* src = Aip + (size_t)r * lda + k0 + c * 8;
            float4 v0 = *(const float4*)src;
            float4 v1 = *(const float4*)(src + 4);
            uint4 hi;
            cvt_hi16(v0, v1, hi);
            *(uint4*)(stg + sw) = hi;
        }
        #pragma unroll
        for (int p = 0; p < 8; p++) {
            int idx = ptid + p * 128;
            int r = idx >> 3, c = idx & 7;
            int sw = r * 128 + ((c ^ (r & 7)) << 4);
            const float* src = Bip + (size_t)r * ldb + k0 + c * 8;
            float4 v0 = *(const float4*)src;
            float4 v1 = *(const float4*)(src + 4);
            uint4 hi, lo;
            cvt_split16(v0, v1, hi, lo);
            *(uint4*)(stg + T64B + sw) = hi;
            *(uint4*)(stg + 2*T64B + sw) = lo;
        }
        BAR_ARRIVE(1 + s);                        // FULL(s)
    }
}

// ---- consumer body (software-pipelined fragments) ----
template<bool BIAS>
__device__ __forceinline__ void big_consumer(
    char* smc, float* C, int ldc, const float* bias,
    int m0, int n0, int iters, int tid)
{
    const int lane = tid & 31;
    const int wid  = tid >> 5;
    const int wm = wid >> 2;
    const int wn = wid & 3;
    const int g  = lane >> 2;
    const int tig = lane & 3;
    const uint32_t sbase = smem_u32(smc);
    const int grp = lane >> 3;
    const int bt  = lane & 7;

    float acc[4][4][4];
    #pragma unroll
    for (int i = 0; i < 4; i++)
        #pragma unroll
        for (int j = 0; j < 4; j++)
            #pragma unroll
            for (int v = 0; v < 4; v++) acc[i][j][v] = 0.f;

    uint32_t ah[2][4][4], bh[2][4][2], bl[2][4][2];

    auto load_frags = [&](uint32_t stg, int kt, int buf) {
        const int cA = kt * 2 + (lane >> 4);
        #pragma unroll
        for (int mi = 0; mi < 4; mi++) {
            int r = wm * 64 + mi * 16 + (lane & 15);
            uint32_t off = (uint32_t)(r * 128 + ((cA ^ (r & 7)) << 4));
            ldsm4(ah[buf][mi], stg + off);
        }
        #pragma unroll
        for (int nip = 0; nip < 2; nip++) {
            int row = wn * 32 + nip * 16 + ((grp >> 1) << 3) + bt;
            int cc  = kt * 2 + (grp & 1);
            uint32_t off = (uint32_t)(row * 128 + ((cc ^ (row & 7)) << 4));
            uint32_t r4[4];
            ldsm4(r4, stg + T64B + off);
            bh[buf][nip*2][0]   = r4[0]; bh[buf][nip*2][1]   = r4[1];
            bh[buf][nip*2+1][0] = r4[2]; bh[buf][nip*2+1][1] = r4[3];
            ldsm4(r4, stg + 2*T64B + off);
            bl[buf][nip*2][0]   = r4[0]; bl[buf][nip*2][1]   = r4[1];
            bl[buf][nip*2+1][0] = r4[2]; bl[buf][nip*2+1][1] = r4[3];
        }
    };

    for (int it = 0; it < iters; it++) {
        const int s = it & 1;
        BAR_SYNC(1 + s);                          // FULL(s)
        const uint32_t stg = sbase + s * STG64B;

        load_frags(stg, 0, 0);
        #pragma unroll
        for (int kt = 0; kt < 4; kt++) {
            const int cur = kt & 1;
            if (kt < 3) load_frags(stg, kt + 1, cur ^ 1);
            #pragma unroll
            for (int mi = 0; mi < 4; mi++)
                #pragma unroll
                for (int ni = 0; ni < 4; ni++) {
                    mma16816(acc[mi][ni], ah[cur][mi], bh[cur][ni]);
                    mma16816(acc[mi][ni], ah[cur][mi], bl[cur][ni]);
                }
        }
        BAR_ARRIVE(4 + s);                        // EMPTY(s)
    }

    #pragma unroll
    for (int mi = 0; mi < 4; mi++) {
        const int r0 = m0 + wm * 64 + mi * 16 + g;
        #pragma unroll
        for (int ni = 0; ni < 4; ni++) {
            const int col = n0 + wn * 32 + ni * 8 + tig * 2;
            float2 v0, v1;
            v0.x = acc[mi][ni][0]; v0.y = acc[mi][ni][1];
            v1.x = acc[mi][ni][2]; v1.y = acc[mi][ni][3];
            if (BIAS) {
                float2 bv = *(const float2*)(bias + col);
                v0.x += bv.x; v0.y += bv.y;
                v1.x += bv.x; v1.y += bv.y;
            }
            *(float2*)(C + (size_t)r0 * ldc + col) = v0;
            *(float2*)(C + (size_t)(r0 + 8) * ldc + col) = v1;
        }
    }
}

// ============================================================
// gemm_big: single-problem BK=64 GEMM (used for out-GEMM)
// ============================================================
template<bool BIAS>
__global__ __launch_bounds__(384, 1)
void gemm_big(const float* __restrict__ A, long Ab, int lda,
              const float* __restrict__ B, long Bb, int ldb,
              float* __restrict__ C, long Cb, int ldc,
              const float* __restrict__ bias, int Kd)
{
    extern __shared__ __align__(16) char smc[];
    const int tid = threadIdx.x;
    const int z = blockIdx.z;
    const float* Ap = A + (size_t)z * Ab;
    const float* Bp = B + (size_t)z * Bb;
    float* Cp = C + (size_t)z * Cb;
    const int m0 = blockIdx.y * 128;
    const int n0 = blockIdx.x * 128;
    const int iters = Kd / 64;

    if ((tid >> 5) >= 8) big_producer(smc, Ap, Bp, lda, ldb, m0, n0, iters, tid);
    else big_consumer<BIAS>(smc, Cp, ldc, bias, m0, n0, iters, tid);
}

// ============================================================
// gemm3: q + xkt + xvt merged (1536 CTAs, flattened 1D grid)
// ============================================================
__global__ __launch_bounds__(384, 1)
void gemm3(const float* __restrict__ x,
           const float* __restrict__ Wq,
           const float* __restrict__ Wk,
           const float* __restrict__ Wv,
           float* __restrict__ q,
           float* __restrict__ xkt,
           float* __restrict__ xvt)
{
    extern __shared__ __align__(16) char smc[];
    const int tid = threadIdx.x;
    int t = blockIdx.x;

    const float *A, *B;
    float* C;
    int m0, n0, ldb, ldc;
    if (t < 512) {
        A = x; B = Wq; C = q;
        m0 = (t >> 3) * 128; n0 = (t & 7) * 128;
        ldb = DD; ldc = DD;
    } else {
        int which = (t >= 1024);
        int u = t - (which ? 1024 : 512);
        int b = u >> 7;
        int rem = u & 127;
        A = which ? Wv : Wk;
        B = x + (size_t)b * LL * DD;
        C = (which ? xvt : xkt) + (size_t)b * DD * LL;
        m0 = (rem >> 4) * 128; n0 = (rem & 15) * 128;
        ldb = DD; ldc = LL;
    }

    if ((tid >> 5) >= 8) big_producer(smc, A, B, DD, ldb, m0, n0, DD / 64, tid);
    else big_consumer<false>(smc, C, ldc, nullptr, m0, n0, DD / 64, tid);
}

// ============================================================
// 128x128 BK=32 warp-specialized 2-MMA split GEMM (proj GEMMs, merged,
// NO split-K: full L=2048 reduction per CTA; 128 CTAs total)
// ============================================================
#define TILEB 8192
#define STGB  (3*TILEB)
#define NSTG  3
#define GEMM_SMEM (NSTG*STGB)        // 73728

__global__ __launch_bounds__(384, 1)
void gemm_ws(const float* __restrict__ A0, const float* __restrict__ A1,
             const float* __restrict__ B0, const float* __restrict__ B1,
             float* __restrict__ C0, float* __restrict__ C1,
             int Kd, int zhalf)
{
    extern __shared__ __align__(16) char smc[];

    const int tid  = threadIdx.x;
    const int lane = tid & 31;
    const int wid  = tid >> 5;

    int z = blockIdx.z;
    const float* A = A0;
    const float* B = B0;
    float* C = C0;
    if (z >= zhalf) { A = A1; B = B1; C = C1; z -= zhalf; }
    B += (size_t)z * DD * LL;
    C += (size_t)z * KK * DD;
    const int m0 = blockIdx.y * 128;
    const int n0 = blockIdx.x * 128;
    const int iters = Kd / 32;

    if (wid >= 8) {
        const int ptid = tid - 256;
        const float* Aip = A + (size_t)m0 * LL;
        const float* Bip = B + (size_t)n0 * LL;

        for (int it = 0; it < iters; it++) {
            const int s = it % NSTG;
            if (it >= NSTG) BAR_SYNC(4 + s);
            const int k0 = it * 32;
            char* stg = smc + s * STGB;
            #pragma unroll
            for (int p = 0; p < 4; p++) {
                int idx = ptid + p * 128;
                int r = idx >> 2, c = idx & 3;
                int sw = (c ^ ((r >> 1) & 3)) * 16;
                {
                    const float* src = Aip + (size_t)r * LL + k0 + c * 8;
                    float4 v0 = *(const float4*)src;
                    float4 v1 = *(const float4*)(src + 4);
                    uint4 hi;
                    cvt_hi16(v0, v1, hi);
                    *(uint4*)(stg + r * 64 + sw) = hi;
                }
                {
                    const float* src = Bip + (size_t)r * LL + k0 + c * 8;
                    float4 v0 = *(const float4*)src;
                    float4 v1 = *(const float4*)(src + 4);
                    uint4 hi, lo;
                    cvt_split16(v0, v1, hi, lo);
                    *(uint4*)(stg + TILEB + r * 64 + sw) = hi;
                    *(uint4*)(stg + 2*TILEB + r * 64 + sw) = lo;
                }
            }
            BAR_ARRIVE(1 + s);
        }
    } else {
        const int wm = wid >> 2;
        const int wn = wid & 3;
        const int g  = lane >> 2;
        const int tig = lane & 3;
        const uint32_t sbase = smem_u32(smc);

        float acc[4][4][4];
        #pragma unroll
        for (int i = 0; i < 4; i++)
            #pragma unroll
            for (int j = 0; j < 4; j++)
                #pragma unroll
                for (int v = 0; v < 4; v++) acc[i][j][v] = 0.f;

        for (int it = 0; it < iters; it++) {
            const int s = it % NSTG;
            BAR_SYNC(1 + s);
            const uint32_t stg = sbase + s * STGB;

            uint32_t ah[2][4][4], bh[2][4][2], bl[2][4][2];
            #pragma unroll
            for (int ks = 0; ks < 2; ks++) {
                const int cA = ks * 2 + (lane >> 4);
                #pragma unroll
                for (int mi = 0; mi < 4; mi++) {
                    int r = wm * 64 + mi * 16 + (lane & 15);
                    uint32_t off = (uint32_t)(r * 64 + ((cA ^ ((r >> 1) & 3)) << 4));
                    ldsm4(ah[ks][mi], stg + off);
                }
                const int cB = ks * 2 + ((lane >> 3) & 1);
                #pragma unroll
                for (int ni = 0; ni < 4; ni++) {
                    int r = wn * 32 + ni * 8 + (lane & 7);
                    uint32_t off = (uint32_t)(r * 64 + ((cB ^ ((r >> 1) & 3)) << 4));
                    ldsm2(bh[ks][ni], stg + TILEB + off);
                    ldsm2(bl[ks][ni], stg + 2*TILEB + off);
                }
            }
            #pragma unroll
            for (int ks = 0; ks < 2; ks++)
                #pragma unroll
                for (int mi = 0; mi < 4; mi++)
                    #pragma unroll
                    for (int ni = 0; ni < 4; ni++) {
                        mma16816(acc[mi][ni], ah[ks][mi], bh[ks][ni]);
                        mma16816(acc[mi][ni], ah[ks][mi], bl[ks][ni]);
                    }
            BAR_ARRIVE(4 + s);
        }

        #pragma unroll
        for (int mi = 0; mi < 4; mi++) {
            const int r0 = m0 + wm * 64 + mi * 16 + g;
            #pragma unroll
            for (int ni = 0; ni < 4; ni++) {
                const int col = n0 + wn * 32 + ni * 8 + tig * 2;
                float2 v0, v1;
                v0.x = acc[mi][ni][0]; v0.y = acc[mi][ni][1];
                v1.x = acc[mi][ni][2]; v1.y = acc[mi][ni][3];
                *(float2*)(C + (size_t)r0 * DD + col) = v0;
                *(float2*)(C + (size_t)(r0 + 8) * DD + col) = v1;
            }
        }
    }
}

// ============================================================
// proj transpose: [L,K] -> [K,L]
// ============================================================
__global__ __launch_bounds__(256)
void transpose_proj(const float* __restrict__ pk, const float* __restrict__ pv,
                    float* __restrict__ okt, float* __restrict__ ovt)
{
    __shared__ float t[32][33];
    const float* src = blockIdx.z ? pv : pk;
    float* dst       = blockIdx.z ? ovt : okt;
    int k0 = blockIdx.x * 32, l0 = blockIdx.y * 32;
    int tx = threadIdx.x, ty = threadIdx.y;
    #pragma unroll
    for (int i = 0; i < 32; i += 8)
        t[ty + i][tx] = src[(size_t)(l0 + ty + i) * KK + k0 + tx];
    __syncthreads();
    #pragma unroll
    for (int i = 0; i < 32; i += 8)
        dst[(size_t)(k0 + ty + i) * LL + l0 + tx] = t[tx][ty + i];
}

// ============================================================
// MMA attention: 128-thread CTA (4 warps, 64 q-rows), 2 CTAs/SM.
// smem: Q 8KB + K hi/lo 64KB; V REUSES the K buffers after softmax.
// 2-MMA split both phases (R14 math).
// ============================================================
#define AQH 0
#define AKH 8192
#define AKL 40960
#define ATTN_SMEM 73728

__global__ __launch_bounds__(128, 2)
void attn_mma()
{
    extern __shared__ __align__(16) char smc[];
    const uint32_t base = smem_u32(smc);

    const int b  = blockIdx.z;
    const int h  = blockIdx.y;
    const int l0 = blockIdx.x * 64;
    const int tid  = threadIdx.x;
    const int lane = tid & 31;
    const int wy   = tid >> 5;          // 0..3
    const int g    = lane >> 2;
    const int tig  = lane & 3;

    // ---- fill Q (64 rows, hi only) ----
    #pragma unroll
    for (int it = 0; it < 4; it++) {
        int idx = tid + it * 128;                 // 0..511
        int r = idx >> 3, c = idx & 7;
        int l = l0 + r;
        const float* src = g_q + ((size_t)(b * LL) + h * 128 + (l >> 4)) * DD
                               + (l & 15) * DH + c * 8;
        float4 v0 = *(const float4*)src;
        float4 v1 = *(const float4*)(src + 4);
        uint4 hi;
        cvt_hi16(v0, v1, hi);
        int sw = r * 128 + ((c ^ (r & 7)) << 4);
        *(uint4*)(smc + AQH + sw) = hi;
    }
    // ---- fill K (hi/lo) ----
    #pragma unroll
    for (int it = 0; it < 16; it++) {
        int idx = tid + it * 128;                 // 0..2047
        int r = idx >> 3, c = idx & 7;
        size_t o = ((size_t)b * KK + r) * DD + h * DH + c * 8;
        float4 a0 = *(const float4*)&g_keys[o];
        float4 a1 = *(const float4*)&g_keys[o + 4];
        uint4 hi, lo;
        cvt_split16(a0, a1, hi, lo);
        int sw = r * 128 + ((c ^ (r & 7)) << 4);
        *(uint4*)(smc + AKH + sw) = hi;
        *(uint4*)(smc + AKL + sw) = lo;
    }
    __syncthreads();

    const int m0w = wy * 16;

    // ---- Q A-fragments (hi only) ----
    uint32_t qa_h[4][4];
    {
        int r = m0w + (lane & 15);
        #pragma unroll
        for (int kt = 0; kt < 4; kt++) {
            int c = kt * 2 + (lane >> 4);
            uint32_t off = (uint32_t)(r * 128 + ((c ^ (r & 7)) << 4));
            ldsm4(qa_h[kt], base + AQH + off);
        }
    }

    // ---- S = Qh Kh^T + Qh Kl^T ----
    float acc[32][4];
    #pragma unroll
    for (int nt = 0; nt < 32; nt++)
        #pragma unroll
        for (int v = 0; v < 4; v++) acc[nt][v] = 0.f;

    #pragma unroll
    for (int nt = 0; nt < 32; nt++) {
        int r = nt * 8 + (lane & 7);
        int c0 = (lane >> 3);
        uint32_t off1 = (uint32_t)(r * 128 + ((c0 ^ (r & 7)) << 4));
        uint32_t off2 = (uint32_t)(r * 128 + (((c0 + 4) ^ (r & 7)) << 4));
        uint32_t kh[8], kl[8];
        ldsm4(kh,     base + AKH + off1);
        ldsm4(kh + 4, base + AKH + off2);
        ldsm4(kl,     base + AKL + off1);
        ldsm4(kl + 4, base + AKL + off2);
        #pragma unroll
        for (int kt = 0; kt < 4; kt++) {
            mma16816(acc[nt], qa_h[kt], kh + kt * 2);
            mma16816(acc[nt], qa_h[kt], kl + kt * 2);
        }
    }

    // ---- softmax (rows g and g+8) ----
    const float SC = 0.125f;
    float mx0 = -1e30f, mx1 = -1e30f;
    #pragma unroll
    for (int nt = 0; nt < 32; nt++) {
        mx0 = fmaxf(mx0, fmaxf(acc[nt][0], acc[nt][1]));
        mx1 = fmaxf(mx1, fmaxf(acc[nt][2], acc[nt][3]));
    }
    #pragma unroll
    for (int o = 1; o <= 2; o <<= 1) {
        mx0 = fmaxf(mx0, __shfl_xor_sync(0xffffffffu, mx0, o));
        mx1 = fmaxf(mx1, __shfl_xor_sync(0xffffffffu, mx1, o));
    }
    const float b0s = mx0 * SC, b1s = mx1 * SC;
    float s0 = 0.f, s1 = 0.f;
    #pragma unroll
    for (int nt = 0; nt < 32; nt++) {
        acc[nt][0] = __expf(acc[nt][0] * SC - b0s);
        acc[nt][1] = __expf(acc[nt][1] * SC - b0s);
        acc[nt][2] = __expf(acc[nt][2] * SC - b1s);
        acc[nt][3] = __expf(acc[nt][3] * SC - b1s);
        s0 += acc[nt][0] + acc[nt][1];
        s1 += acc[nt][2] + acc[nt][3];
    }
    #pragma unroll
    for (int o = 1; o <= 2; o <<= 1) {
        s0 += __shfl_xor_sync(0xffffffffu, s0, o);
        s1 += __shfl_xor_sync(0xffffffffu, s1, o);
    }
    const float inv0 = 1.f / s0, inv1 = 1.f / s1;

    // ---- all warps done reading K -> refill buffers with V ----
    __syncthreads();
    #pragma unroll
    for (int it = 0; it < 16; it++) {
        int idx = tid + it * 128;
        int r = idx >> 3, c = idx & 7;
        size_t o = ((size_t)b * KK + r) * DD + h * DH + c * 8;
        float4 a0 = *(const float4*)&g_vals[o];
        float4 a1 = *(const float4*)&g_vals[o + 4];
        uint4 hi, lo;
        cvt_split16(a0, a1, hi, lo);
        int sw = r * 128 + ((c ^ (r & 7)) << 4);
        *(uint4*)(smc + AKH + sw) = hi;
        *(uint4*)(smc + AKL + sw) = lo;
    }
    __syncthreads();

    // ---- O = Ph Vh + Ph Vl ----
    float oac[8][4];
    #pragma unroll
    for (int nj = 0; nj < 8; nj++)
        #pragma unroll
        for (int v = 0; v < 4; v++) oac[nj][v] = 0.f;

    #pragma unroll
    for (int kt = 0; kt < 16; kt++) {
        uint32_t ph[4];
        #pragma unroll
        for (int half_ = 0; half_ < 2; half_++) {
            const float* c = acc[2 * kt + half_];
            __half2 h0 = __floats2half2_rn(c[0], c[1]);
            __half2 h1 = __floats2half2_rn(c[2], c[3]);
            ph[half_ * 2 + 0] = *(uint32_t*)&h0;
            ph[half_ * 2 + 1] = *(uint32_t*)&h1;
        }
        int rv = kt * 16 + (lane & 15);
        #pragma unroll
        for (int nj = 0; nj < 8; nj++) {
            uint32_t off = (uint32_t)(rv * 128 + ((nj ^ (rv & 7)) << 4));
            uint32_t vh[2], vl[2];
            ldsm2t(vh, base + AKH + off);
            ldsm2t(vl, base + AKL + off);
            mma16816(oac[nj], ph, vh);
            mma16816(oac[nj], ph, vl);
        }
    }

    {
        const int r0 = l0 + m0w + g;
        const size_t orow = ((size_t)(b * LL) + r0) * DD + h * DH;
        #pragma unroll
        for (int nj = 0; nj < 8; nj++) {
            float2 v0, v1;
            v0.x = oac[nj][0] * inv0; v0.y = oac[nj][1] * inv0;
            v1.x = oac[nj][2] * inv1; v1.y = oac[nj][3] * inv1;
            *(float2*)&g_ctx[orow + nj * 8 + tig * 2] = v0;
            *(float2*)&g_ctx[orow + (size_t)8 * DD + nj * 8 + tig * 2] = v1;
        }
    }
}

// ============================================================
extern "C" void kernel_launch(void* const* d_in, const int* in_sizes, int n_in,
                              void* d_out, int out_size)
{
    const float* x      = (const float*)d_in[0];
    const float* Wq     = (const float*)d_in[1];
    const float* Wk     = (const float*)d_in[2];
    const float* Wv     = (const float*)d_in[3];
    const float* proj_k = (const float*)d_in[4];
    const float* proj_v = (const float*)d_in[5];
    const float* Wo     = (const float*)d_in[6];
    const float* bo     = (const float*)d_in[7];
    float* out = (float*)d_out;

    float *q, *xkt, *xvt, *projkt, *projvt, *keys, *vals, *ctx;
    cudaGetSymbolAddress((void**)&q,      g_q);
    cudaGetSymbolAddress((void**)&xkt,    g_xkt);
    cudaGetSymbolAddress((void**)&xvt,    g_xvt);
    cudaGetSymbolAddress((void**)&projkt, g_projkt);
    cudaGetSymbolAddress((void**)&projvt, g_projvt);
    cudaGetSymbolAddress((void**)&keys,   g_keys);
    cudaGetSymbolAddress((void**)&vals,   g_vals);
    cudaGetSymbolAddress((void**)&ctx,    g_ctx);

    cudaFuncSetAttribute(gemm3,          cudaFuncAttributeMaxDynamicSharedMemorySize, GEMM64_SMEM);
    cudaFuncSetAttribute(gemm_big<true>, cudaFuncAttributeMaxDynamicSharedMemorySize, GEMM64_SMEM);
    cudaFuncSetAttribute(gemm_ws,        cudaFuncAttributeMaxDynamicSharedMemorySize, GEMM_SMEM);
    cudaFuncSetAttribute(attn_mma,       cudaFuncAttributeMaxDynamicSharedMemorySize, ATTN_SMEM);

    // proj_k / proj_v -> transposed [K,L]
    transpose_proj<<<dim3(KK/32, LL/32, 2), dim3(32, 8)>>>(proj_k, proj_v, projkt, projvt);

    // q + xkt + xvt merged (1536 CTAs, one wave-tail)
    gemm3<<<1536, 384, GEMM64_SMEM>>>(x, Wq, Wk, Wv, q, xkt, xvt);

    // keys/vals merged, NO split-K
    gemm_ws<<<dim3(DD/128, KK/128, 2*BB), 384, GEMM_SMEM>>>(
        projkt, projvt, xkt, xvt, keys, vals, LL, BB);

    // MMA attention (128-thread CTAs, 2/SM, V reuses K smem)
    attn_mma<<<dim3(LL/64, HH, BB), 128, ATTN_SMEM>>>();

    // out = ctx @ Wo^T + bo
    gemm_big<true><<<dim3(DD/128, MROWS/128, 1), 384, GEMM64_SMEM>>>(
        ctx, 0, DD, Wo, 0, DD, out, 0, DD, bo, DD);
}